// round 2
// baseline (speedup 1.0000x reference)
#include <cuda_runtime.h>

// Problem constants
#define DIM   512
#define NH    8
#define DH    64
#define NLAT  128
#define NTOK  16
#define BATCH 1024
#define MQ    (BATCH * NTOK)    // 16384
#define MKV   (BATCH * NLAT)    // 131072

// Scratch
__device__ float g_q  [MQ  * DIM];
__device__ float g_k  [MKV * DIM];
__device__ float g_v  [MKV * DIM];
__device__ float g_att[MQ  * DIM];

typedef unsigned long long u64;

// packed fp32x2 FMA: acc = a*b + acc (each half IEEE fp32 FMA)
#define FMA2(acc, a, b) asm("fma.rn.f32x2 %0, %1, %2, %3;" : "=l"(acc) : "l"(a), "l"(b), "l"(acc))

__device__ __forceinline__ u64 dup_f32(float x) {
    u64 r; asm("mov.b64 %0, {%1, %1};" : "=l"(r) : "f"(x)); return r;
}
__device__ __forceinline__ void unpack2(float& lo, float& hi, u64 v) {
    asm("mov.b64 {%0, %1}, %2;" : "=f"(lo), "=f"(hi) : "l"(v));
}

// ---------------------------------------------------------------------------
// C = A @ W^T (+bias).  BM=128, BN=128, BK=16, 256 threads, 8x8 per thread
// using packed f32x2 FMA.  Grid: (DIM/128, M/128)
// ---------------------------------------------------------------------------
__global__ __launch_bounds__(256) void gemm128(const float* __restrict__ A,
                                               const float* __restrict__ W,
                                               const float* __restrict__ bias,
                                               float* __restrict__ C)
{
    __shared__ float As[16][128];
    __shared__ float Bs[16][128];

    const int t  = threadIdx.x;
    const int bm = blockIdx.y * 128;
    const int bn = blockIdx.x * 128;

    const int tx4 = (t & 15) * 4;      // n: tx4 and 64+tx4
    const int ty4 = ((t >> 4) & 15) * 4; // m: ty4 and 64+ty4

    const int lr  = t & 127;           // staging row (conflict-free STS)
    const int lc8 = (t >> 7) * 8;      // col base 0 or 8

    u64 acc[8][4];
#pragma unroll
    for (int i = 0; i < 8; i++)
#pragma unroll
        for (int j = 0; j < 4; j++) acc[i][j] = 0ULL;

    for (int kt = 0; kt < DIM; kt += 16) {
        float4 a0 = *(const float4*)&A[(size_t)(bm + lr) * DIM + kt + lc8];
        float4 a1 = *(const float4*)&A[(size_t)(bm + lr) * DIM + kt + lc8 + 4];
        float4 w0 = *(const float4*)&W[(size_t)(bn + lr) * DIM + kt + lc8];
        float4 w1 = *(const float4*)&W[(size_t)(bn + lr) * DIM + kt + lc8 + 4];
        As[lc8 + 0][lr] = a0.x; As[lc8 + 1][lr] = a0.y;
        As[lc8 + 2][lr] = a0.z; As[lc8 + 3][lr] = a0.w;
        As[lc8 + 4][lr] = a1.x; As[lc8 + 5][lr] = a1.y;
        As[lc8 + 6][lr] = a1.z; As[lc8 + 7][lr] = a1.w;
        Bs[lc8 + 0][lr] = w0.x; Bs[lc8 + 1][lr] = w0.y;
        Bs[lc8 + 2][lr] = w0.z; Bs[lc8 + 3][lr] = w0.w;
        Bs[lc8 + 4][lr] = w1.x; Bs[lc8 + 5][lr] = w1.y;
        Bs[lc8 + 6][lr] = w1.z; Bs[lc8 + 7][lr] = w1.w;
        __syncthreads();

#pragma unroll
        for (int k = 0; k < 16; k++) {
            float4 va0 = *(const float4*)&As[k][ty4];
            float4 va1 = *(const float4*)&As[k][64 + ty4];
            ulonglong2 vb0 = *(const ulonglong2*)&Bs[k][tx4];
            ulonglong2 vb1 = *(const ulonglong2*)&Bs[k][64 + tx4];
            u64 ad[8] = {dup_f32(va0.x), dup_f32(va0.y), dup_f32(va0.z), dup_f32(va0.w),
                         dup_f32(va1.x), dup_f32(va1.y), dup_f32(va1.z), dup_f32(va1.w)};
#pragma unroll
            for (int mi = 0; mi < 8; mi++) {
                FMA2(acc[mi][0], ad[mi], vb0.x);
                FMA2(acc[mi][1], ad[mi], vb0.y);
                FMA2(acc[mi][2], ad[mi], vb1.x);
                FMA2(acc[mi][3], ad[mi], vb1.y);
            }
        }
        __syncthreads();
    }

    float4 bb0 = make_float4(0.f, 0.f, 0.f, 0.f);
    float4 bb1 = make_float4(0.f, 0.f, 0.f, 0.f);
    if (bias) {
        bb0 = *(const float4*)&bias[bn + tx4];
        bb1 = *(const float4*)&bias[bn + 64 + tx4];
    }

#pragma unroll
    for (int mi = 0; mi < 8; mi++) {
        int row = bm + ((mi < 4) ? (ty4 + mi) : (64 + ty4 + mi - 4));
        float c0, c1, c2, c3;
        unpack2(c0, c1, acc[mi][0]); unpack2(c2, c3, acc[mi][1]);
        *(float4*)&C[(size_t)row * DIM + bn + tx4] =
            make_float4(c0 + bb0.x, c1 + bb0.y, c2 + bb0.z, c3 + bb0.w);
        unpack2(c0, c1, acc[mi][2]); unpack2(c2, c3, acc[mi][3]);
        *(float4*)&C[(size_t)row * DIM + bn + 64 + tx4] =
            make_float4(c0 + bb1.x, c1 + bb1.y, c2 + bb1.z, c3 + bb1.w);
    }
}

// ---------------------------------------------------------------------------
// Fused K + V projection with mask row skipping.  BM=32 (fine-grained skip),
// BN=128 over virtual N'=1024 (K||V), 128 threads, 4x8 per thread, f32x2.
// Grid: (1024/128 = 8, 131072/32 = 4096)
// ---------------------------------------------------------------------------
__global__ __launch_bounds__(128) void gemm_kv(const float* __restrict__ L,
                                               const float* __restrict__ Wk,
                                               const float* __restrict__ Wv)
{
    const int bm    = blockIdx.y * 32;
    const int b     = bm >> 7;
    const int j0    = bm & 127;
    const int limit = b & 127;
    if (j0 > limit) return;            // fully masked tile: rows never read

    const int bnv = blockIdx.x * 128;
    const float* __restrict__ W;
    float* __restrict__ Cout;
    int bn;
    if (bnv < 512) { W = Wk; Cout = g_k; bn = bnv; }
    else           { W = Wv; Cout = g_v; bn = bnv - 512; }

    __shared__ float As[16][32];
    __shared__ float Ws[16][128];

    const int t   = threadIdx.x;
    const int tx4 = (t & 15) * 4;      // n: tx4, 64+tx4
    const int ty4 = (t >> 4) * 4;      // m: ty4 (0..28)

    const int ar  = t & 31;            // A staging row
    const int ac4 = (t >> 5) * 4;      // A staging col base (0,4,8,12)
    const int wr  = t & 63;            // W staging rows wr, wr+64
    const int wc8 = (t >> 6) * 8;      // W staging col base (0 or 8)

    u64 acc[4][4];
#pragma unroll
    for (int i = 0; i < 4; i++)
#pragma unroll
        for (int j = 0; j < 4; j++) acc[i][j] = 0ULL;

    for (int kt = 0; kt < DIM; kt += 16) {
        float4 a0 = *(const float4*)&L[(size_t)(bm + ar) * DIM + kt + ac4];
        float4 w0 = *(const float4*)&W[(size_t)(bn + wr) * DIM + kt + wc8];
        float4 w1 = *(const float4*)&W[(size_t)(bn + wr) * DIM + kt + wc8 + 4];
        float4 w2 = *(const float4*)&W[(size_t)(bn + wr + 64) * DIM + kt + wc8];
        float4 w3 = *(const float4*)&W[(size_t)(bn + wr + 64) * DIM + kt + wc8 + 4];

        As[ac4 + 0][ar] = a0.x; As[ac4 + 1][ar] = a0.y;
        As[ac4 + 2][ar] = a0.z; As[ac4 + 3][ar] = a0.w;
        Ws[wc8 + 0][wr] = w0.x; Ws[wc8 + 1][wr] = w0.y;
        Ws[wc8 + 2][wr] = w0.z; Ws[wc8 + 3][wr] = w0.w;
        Ws[wc8 + 4][wr] = w1.x; Ws[wc8 + 5][wr] = w1.y;
        Ws[wc8 + 6][wr] = w1.z; Ws[wc8 + 7][wr] = w1.w;
        Ws[wc8 + 0][wr + 64] = w2.x; Ws[wc8 + 1][wr + 64] = w2.y;
        Ws[wc8 + 2][wr + 64] = w2.z; Ws[wc8 + 3][wr + 64] = w2.w;
        Ws[wc8 + 4][wr + 64] = w3.x; Ws[wc8 + 5][wr + 64] = w3.y;
        Ws[wc8 + 6][wr + 64] = w3.z; Ws[wc8 + 7][wr + 64] = w3.w;
        __syncthreads();

#pragma unroll
        for (int k = 0; k < 16; k++) {
            float4 va = *(const float4*)&As[k][ty4];
            ulonglong2 vb0 = *(const ulonglong2*)&Ws[k][tx4];
            ulonglong2 vb1 = *(const ulonglong2*)&Ws[k][64 + tx4];
            u64 ad[4] = {dup_f32(va.x), dup_f32(va.y), dup_f32(va.z), dup_f32(va.w)};
#pragma unroll
            for (int mi = 0; mi < 4; mi++) {
                FMA2(acc[mi][0], ad[mi], vb0.x);
                FMA2(acc[mi][1], ad[mi], vb0.y);
                FMA2(acc[mi][2], ad[mi], vb1.x);
                FMA2(acc[mi][3], ad[mi], vb1.y);
            }
        }
        __syncthreads();
    }

#pragma unroll
    for (int mi = 0; mi < 4; mi++) {
        int j = j0 + ty4 + mi;
        if (j <= limit) {
            float c0, c1, c2, c3;
            unpack2(c0, c1, acc[mi][0]); unpack2(c2, c3, acc[mi][1]);
            *(float4*)&Cout[(size_t)(bm + ty4 + mi) * DIM + bn + tx4] =
                make_float4(c0, c1, c2, c3);
            unpack2(c0, c1, acc[mi][2]); unpack2(c2, c3, acc[mi][3]);
            *(float4*)&Cout[(size_t)(bm + ty4 + mi) * DIM + bn + 64 + tx4] =
                make_float4(c0, c1, c2, c3);
        }
    }
}

// ---------------------------------------------------------------------------
// Attention: one block per (b, h); 128 threads.
// ---------------------------------------------------------------------------
__global__ __launch_bounds__(128) void attn_kernel()
{
    const int b = blockIdx.x;
    const int h = blockIdx.y;
    const int t = threadIdx.x;
    const int limit = b & 127;
    const int nj = limit + 1;

    __shared__ float qs[NTOK][DH + 1];
    __shared__ float ps[NTOK][NLAT + 1];

#pragma unroll
    for (int u = 0; u < 8; u++) {
        int e = t + u * 128;
        int row = e >> 6, d = e & 63;
        qs[row][d] = g_q[(size_t)(b * NTOK + row) * DIM + h * DH + d];
    }
    __syncthreads();

    {
        const int i = t & 15;
        const int jg = t >> 4;
        for (int j = jg; j < nj; j += 8) {
            const float4* k4 = (const float4*)&g_k[(size_t)(b * NLAT + j) * DIM + h * DH];
            float s = 0.f;
#pragma unroll
            for (int d4 = 0; d4 < 16; d4++) {
                float4 kk = k4[d4];
                s += qs[i][d4 * 4 + 0] * kk.x + qs[i][d4 * 4 + 1] * kk.y
                   + qs[i][d4 * 4 + 2] * kk.z + qs[i][d4 * 4 + 3] * kk.w;
            }
            ps[i][j] = s * 0.125f;
        }
    }
    __syncthreads();

    if (t < NTOK) {
        float m = -1e30f;
        for (int j = 0; j < nj; j++) m = fmaxf(m, ps[t][j]);
        float s = 0.f;
        for (int j = 0; j < nj; j++) { float e = expf(ps[t][j] - m); ps[t][j] = e; s += e; }
        float inv = 1.f / s;
        for (int j = 0; j < nj; j++) ps[t][j] *= inv;
    }
    __syncthreads();

    {
        const int d  = t & 63;
        const int i0 = t >> 6;
        float acc[8];
#pragma unroll
        for (int ii = 0; ii < 8; ii++) acc[ii] = 0.f;
        for (int j = 0; j < nj; j++) {
            float vv = g_v[(size_t)(b * NLAT + j) * DIM + h * DH + d];
#pragma unroll
            for (int ii = 0; ii < 8; ii++)
                acc[ii] += ps[i0 + 2 * ii][j] * vv;
        }
#pragma unroll
        for (int ii = 0; ii < 8; ii++) {
            int i = i0 + 2 * ii;
            g_att[(size_t)(b * NTOK + i) * DIM + h * DH + d] = acc[ii];
        }
    }
}

// ---------------------------------------------------------------------------
extern "C" void kernel_launch(void* const* d_in, const int* in_sizes, int n_in,
                              void* d_out, int out_size)
{
    const float* x  = (const float*)d_in[0];
    const float* l  = (const float*)d_in[1];
    const float* Wq = (const float*)d_in[2];
    const float* Wk = (const float*)d_in[3];
    const float* Wv = (const float*)d_in[4];
    const float* Wo = (const float*)d_in[5];
    const float* bo = (const float*)d_in[6];
    float* out = (float*)d_out;

    float *pq, *pa;
    cudaGetSymbolAddress((void**)&pq, g_q);
    cudaGetSymbolAddress((void**)&pa, g_att);

    gemm128<<<dim3(4, MQ / 128), 256>>>(x, Wq, nullptr, pq);
    gemm_kv<<<dim3(8, MKV / 32), 128>>>(l, Wk, Wv);
    attn_kernel<<<dim3(BATCH, NH), 128>>>();
    gemm128<<<dim3(4, MQ / 128), 256>>>(pa, Wo, bo, out);
}

// round 4
// speedup vs baseline: 2.8086x; 2.8086x over previous
#include <cuda_runtime.h>
#include <cuda_bf16.h>
#include <cstdint>

// ---------------------------------------------------------------- constants
#define DIM   512
#define NH    8
#define DH    64
#define NLAT  128
#define NTOK  16
#define BATCH 1024
#define MQ    (BATCH * NTOK)     // 16384 query rows
#define MKV_C 66048              // compacted K/V rows: 8 * 128*129/2
#define GRP_OFF 8256             // rows per 128-batch group

#define PAD   72                 // smem row stride (bf16 elems) -> conflict-free ldmatrix

// ---------------------------------------------------------------- scratch
__device__ float g_q  [MQ    * DIM];
__device__ float g_k  [MKV_C * DIM];
__device__ float g_v  [MKV_C * DIM];
__device__ float g_att[MQ    * DIM];

__device__ __nv_bfloat16 g_xh[MQ * DIM],    g_xl[MQ * DIM];
__device__ __nv_bfloat16 g_lh[MKV_C * DIM], g_ll[MKV_C * DIM];
__device__ __nv_bfloat16 g_ah[MQ * DIM],    g_al[MQ * DIM];
__device__ __nv_bfloat16 g_wh[4 * DIM * DIM], g_wl[4 * DIM * DIM]; // Wq|Wk|Wv|Wo

// ---------------------------------------------------------------- helpers
__device__ __forceinline__ uint32_t smem_u32(const void* p) {
    uint32_t a;
    asm("{ .reg .u64 t; cvta.to.shared.u64 t, %1; cvt.u32.u64 %0, t; }"
        : "=r"(a) : "l"(p));
    return a;
}

#define LDMX4(r0, r1, r2, r3, addr)                                          \
    asm volatile("ldmatrix.sync.aligned.m8n8.x4.shared.b16 {%0,%1,%2,%3}, [%4];" \
                 : "=r"(r0), "=r"(r1), "=r"(r2), "=r"(r3) : "r"(addr))

#define MMA16816(d, a, b0, b1)                                               \
    asm volatile("mma.sync.aligned.m16n8k16.row.col.f32.bf16.bf16.f32 "      \
                 "{%0,%1,%2,%3},{%4,%5,%6,%7},{%8,%9},{%0,%1,%2,%3};"        \
                 : "+f"((d)[0]), "+f"((d)[1]), "+f"((d)[2]), "+f"((d)[3])    \
                 : "r"((a)[0]), "r"((a)[1]), "r"((a)[2]), "r"((a)[3]),       \
                   "r"(b0), "r"(b1))

// ---------------------------------------------------------------- hi/lo split
__device__ __forceinline__ void split2(float x, float y, uint32_t& hi, uint32_t& lo) {
    __nv_bfloat16 hx = __float2bfloat16(x), hy = __float2bfloat16(y);
    __nv_bfloat16 lx = __float2bfloat16(x - __bfloat162float(hx));
    __nv_bfloat16 ly = __float2bfloat16(y - __bfloat162float(hy));
    __nv_bfloat162 H = __halves2bfloat162(hx, hy);
    __nv_bfloat162 L = __halves2bfloat162(lx, ly);
    hi = *reinterpret_cast<uint32_t*>(&H);
    lo = *reinterpret_cast<uint32_t*>(&L);
}

__global__ __launch_bounds__(256) void conv_hilo(const float* __restrict__ src,
                                                 __nv_bfloat16* __restrict__ hi,
                                                 __nv_bfloat16* __restrict__ lo, int n4)
{
    int i = blockIdx.x * 256 + threadIdx.x;
    if (i >= n4) return;
    float4 v = ((const float4*)src)[i];
    uint2 H, L;
    split2(v.x, v.y, H.x, L.x);
    split2(v.z, v.w, H.y, L.y);
    ((uint2*)hi)[i] = H;
    ((uint2*)lo)[i] = L;
}

// gather+split live latent rows into compact layout (row = off(b)+j)
__global__ __launch_bounds__(128) void gather_l(const float* __restrict__ L)
{
    const int b = blockIdx.x, j = blockIdx.y;
    const int m = b & 127;
    if (j > m) return;
    const int r = (b >> 7) * GRP_OFF + (m * (m + 1)) / 2 + j;
    const int t = threadIdx.x;
    float4 v = ((const float4*)&L[(size_t)(b * NLAT + j) * DIM])[t];
    uint2 H, Lo;
    split2(v.x, v.y, H.x, Lo.x);
    split2(v.z, v.w, H.y, Lo.y);
    ((uint2*)&g_lh[(size_t)r * DIM])[t] = H;
    ((uint2*)&g_ll[(size_t)r * DIM])[t] = Lo;
}

// ---------------------------------------------------------------- MMA GEMM
// C(M,512) = A(M,512) @ W(512,512)^T (+bias); A,W as bf16 hi/lo.
// 3-pass error compensation: Ah*Wh + Ah*Wl + Al*Wh (fp32 accum).
// CTA tile 128x128, 8 warps (2x4) each 64x32; BK=64; grid (4, M/128).
__global__ __launch_bounds__(256, 2) void gemm_mma(
    const __nv_bfloat16* __restrict__ Ah, const __nv_bfloat16* __restrict__ Al,
    const __nv_bfloat16* __restrict__ Wh, const __nv_bfloat16* __restrict__ Wl,
    const float* __restrict__ bias, float* __restrict__ C)
{
    extern __shared__ __nv_bfloat16 sm[];
    __nv_bfloat16* sAh = sm;
    __nv_bfloat16* sAl = sAh + 128 * PAD;
    __nv_bfloat16* sBh = sAl + 128 * PAD;
    __nv_bfloat16* sBl = sBh + 128 * PAD;

    const int t  = threadIdx.x;
    const int bm = blockIdx.y * 128;
    const int bn = blockIdx.x * 128;
    const int w = t >> 5, lane = t & 31;
    const int wy = w >> 2, wx = w & 3;      // warp tile at (wy*64, wx*32)
    const int r8 = lane & 7, sub = lane >> 3;

    const uint32_t aAh = smem_u32(sAh), aAl = smem_u32(sAl);
    const uint32_t aBh = smem_u32(sBh), aBl = smem_u32(sBl);

    float acc[4][4][4];
#pragma unroll
    for (int mi = 0; mi < 4; mi++)
#pragma unroll
        for (int ni = 0; ni < 4; ni++)
#pragma unroll
            for (int e = 0; e < 4; e++) acc[mi][ni][e] = 0.f;

    // global staging: thread -> row t/2, k-chunks (t&1)*4 .. +3 (8 bf16 each)
    const int grow = t >> 1;
    const int gkc  = (t & 1) * 4;

    // ldmatrix lane-address offsets (elements)
    // A: row = base_m + (sub&1)*8 + r8, col = k0 + (sub>>1)*8
    const int aRow = (sub & 1) * 8 + r8;
    const int aCol = (sub >> 1) * 8;
    // B: row = base_n + (sub>>1)*8 + r8, col = k0 + (sub&1)*8
    const int bRow = (sub >> 1) * 8 + r8;
    const int bCol = (sub & 1) * 8;

    for (int ch = 0; ch < 8; ch++) {
        const int kt = ch * 64;
        const uint4* pAh = (const uint4*)&Ah[(size_t)(bm + grow) * DIM + kt + gkc * 8];
        const uint4* pAl = (const uint4*)&Al[(size_t)(bm + grow) * DIM + kt + gkc * 8];
        const uint4* pWh = (const uint4*)&Wh[(size_t)(bn + grow) * DIM + kt + gkc * 8];
        const uint4* pWl = (const uint4*)&Wl[(size_t)(bn + grow) * DIM + kt + gkc * 8];
#pragma unroll
        for (int u = 0; u < 4; u++) {
            const int soff = grow * PAD + (gkc + u) * 8;
            *(uint4*)&sAh[soff] = pAh[u];
            *(uint4*)&sAl[soff] = pAl[u];
            *(uint4*)&sBh[soff] = pWh[u];
            *(uint4*)&sBl[soff] = pWl[u];
        }
        __syncthreads();

#pragma unroll
        for (int k16 = 0; k16 < 4; k16++) {
            const int k0 = k16 * 16;
            uint32_t ah[4][4], al[4][4];
#pragma unroll
            for (int mi = 0; mi < 4; mi++) {
                const uint32_t off = (uint32_t)(((wy * 64 + mi * 16 + aRow) * PAD + k0 + aCol) * 2);
                LDMX4(ah[mi][0], ah[mi][1], ah[mi][2], ah[mi][3], aAh + off);
                LDMX4(al[mi][0], al[mi][1], al[mi][2], al[mi][3], aAl + off);
            }
            uint32_t bh[8], bl[8];
#pragma unroll
            for (int p = 0; p < 2; p++) {   // n-tile pairs: p covers ni=2p, 2p+1
                const uint32_t off = (uint32_t)(((wx * 32 + p * 16 + bRow) * PAD + k0 + bCol) * 2);
                LDMX4(bh[p * 4 + 0], bh[p * 4 + 1], bh[p * 4 + 2], bh[p * 4 + 3], aBh + off);
                LDMX4(bl[p * 4 + 0], bl[p * 4 + 1], bl[p * 4 + 2], bl[p * 4 + 3], aBl + off);
            }
#pragma unroll
            for (int mi = 0; mi < 4; mi++)
#pragma unroll
                for (int ni = 0; ni < 4; ni++) {
                    MMA16816(acc[mi][ni], ah[mi], bh[ni * 2], bh[ni * 2 + 1]);
                    MMA16816(acc[mi][ni], ah[mi], bl[ni * 2], bl[ni * 2 + 1]);
                    MMA16816(acc[mi][ni], al[mi], bh[ni * 2], bh[ni * 2 + 1]);
                }
        }
        __syncthreads();
    }

    // epilogue
    const int g = lane >> 2, tg = lane & 3;
#pragma unroll
    for (int mi = 0; mi < 4; mi++) {
        const int row0 = bm + wy * 64 + mi * 16 + g;
#pragma unroll
        for (int ni = 0; ni < 4; ni++) {
            const int col = bn + wx * 32 + ni * 8 + tg * 2;
            float b0 = 0.f, b1 = 0.f;
            if (bias) { b0 = bias[col]; b1 = bias[col + 1]; }
            *(float2*)&C[(size_t)row0 * DIM + col] =
                make_float2(acc[mi][ni][0] + b0, acc[mi][ni][1] + b1);
            *(float2*)&C[(size_t)(row0 + 8) * DIM + col] =
                make_float2(acc[mi][ni][2] + b0, acc[mi][ni][3] + b1);
        }
    }
}

// ---------------------------------------------------------------- attention
__global__ __launch_bounds__(128) void attn_kernel()
{
    const int b = blockIdx.x;
    const int h = blockIdx.y;
    const int t = threadIdx.x;
    const int m = b & 127;
    const int nj = m + 1;
    const size_t kvbase = (size_t)((b >> 7) * GRP_OFF + (m * (m + 1)) / 2);

    __shared__ float qs[NTOK][DH + 1];
    __shared__ float ps[NTOK][NLAT + 1];

#pragma unroll
    for (int u = 0; u < 8; u++) {
        int e = t + u * 128;
        qs[e >> 6][e & 63] = g_q[(size_t)(b * NTOK + (e >> 6)) * DIM + h * DH + (e & 63)];
    }
    __syncthreads();

    {
        const int i = t & 15;
        const int jg = t >> 4;
        for (int j = jg; j < nj; j += 8) {
            const float4* k4 = (const float4*)&g_k[(kvbase + j) * DIM + h * DH];
            float s = 0.f;
#pragma unroll
            for (int d4 = 0; d4 < 16; d4++) {
                float4 kk = k4[d4];
                s += qs[i][d4 * 4 + 0] * kk.x + qs[i][d4 * 4 + 1] * kk.y
                   + qs[i][d4 * 4 + 2] * kk.z + qs[i][d4 * 4 + 3] * kk.w;
            }
            ps[i][j] = s * 0.125f;
        }
    }
    __syncthreads();

    if (t < NTOK) {
        float mx = -1e30f;
        for (int j = 0; j < nj; j++) mx = fmaxf(mx, ps[t][j]);
        float s = 0.f;
        for (int j = 0; j < nj; j++) { float e = expf(ps[t][j] - mx); ps[t][j] = e; s += e; }
        float inv = 1.f / s;
        for (int j = 0; j < nj; j++) ps[t][j] *= inv;
    }
    __syncthreads();

    {
        const int d  = t & 63;
        const int i0 = t >> 6;
        float acc[8];
#pragma unroll
        for (int ii = 0; ii < 8; ii++) acc[ii] = 0.f;
        for (int j = 0; j < nj; j++) {
            float vv = g_v[(kvbase + j) * DIM + h * DH + d];
#pragma unroll
            for (int ii = 0; ii < 8; ii++)
                acc[ii] += ps[i0 + 2 * ii][j] * vv;
        }
#pragma unroll
        for (int ii = 0; ii < 8; ii++)
            g_att[(size_t)(b * NTOK + i0 + 2 * ii) * DIM + h * DH + d] = acc[ii];
    }
}

// ---------------------------------------------------------------- launch
extern "C" void kernel_launch(void* const* d_in, const int* in_sizes, int n_in,
                              void* d_out, int out_size)
{
    const float* x  = (const float*)d_in[0];
    const float* l  = (const float*)d_in[1];
    const float* Wq = (const float*)d_in[2];
    const float* Wk = (const float*)d_in[3];
    const float* Wv = (const float*)d_in[4];
    const float* Wo = (const float*)d_in[5];
    const float* bo = (const float*)d_in[6];
    float* out = (float*)d_out;

    float *pq, *pa;
    __nv_bfloat16 *pxh, *pxl, *pah, *pal, *pwh, *pwl, *plh, *pll;
    cudaGetSymbolAddress((void**)&pq,  g_q);
    cudaGetSymbolAddress((void**)&pa,  g_att);
    cudaGetSymbolAddress((void**)&pxh, g_xh);
    cudaGetSymbolAddress((void**)&pxl, g_xl);
    cudaGetSymbolAddress((void**)&pah, g_ah);
    cudaGetSymbolAddress((void**)&pal, g_al);
    cudaGetSymbolAddress((void**)&pwh, g_wh);
    cudaGetSymbolAddress((void**)&pwl, g_wl);
    cudaGetSymbolAddress((void**)&plh, g_lh);
    cudaGetSymbolAddress((void**)&pll, g_ll);

    float *pk, *pv;
    cudaGetSymbolAddress((void**)&pk, g_k);
    cudaGetSymbolAddress((void**)&pv, g_v);

    const int SMEMSZ = 4 * 128 * PAD * 2;        // 73728 B
    static int cfg_done = 0;
    cudaFuncSetAttribute(gemm_mma, cudaFuncAttributeMaxDynamicSharedMemorySize, SMEMSZ);
    (void)cfg_done;

    const int WSZ = DIM * DIM;

    // hi/lo splits
    conv_hilo<<<(MQ * DIM / 4 + 255) / 256, 256>>>(x, pxh, pxl, MQ * DIM / 4);
    conv_hilo<<<(WSZ / 4 + 255) / 256, 256>>>(Wq, pwh + 0 * WSZ, pwl + 0 * WSZ, WSZ / 4);
    conv_hilo<<<(WSZ / 4 + 255) / 256, 256>>>(Wk, pwh + 1 * WSZ, pwl + 1 * WSZ, WSZ / 4);
    conv_hilo<<<(WSZ / 4 + 255) / 256, 256>>>(Wv, pwh + 2 * WSZ, pwl + 2 * WSZ, WSZ / 4);
    conv_hilo<<<(WSZ / 4 + 255) / 256, 256>>>(Wo, pwh + 3 * WSZ, pwl + 3 * WSZ, WSZ / 4);
    gather_l<<<dim3(BATCH, NLAT), 128>>>(l);

    // Q projection
    gemm_mma<<<dim3(4, MQ / 128), 256, SMEMSZ>>>(pxh, pxl, pwh + 0 * WSZ, pwl + 0 * WSZ, nullptr, pq);
    // K / V projections on compact rows
    gemm_mma<<<dim3(4, MKV_C / 128), 256, SMEMSZ>>>(plh, pll, pwh + 1 * WSZ, pwl + 1 * WSZ, nullptr, pk);
    gemm_mma<<<dim3(4, MKV_C / 128), 256, SMEMSZ>>>(plh, pll, pwh + 2 * WSZ, pwl + 2 * WSZ, nullptr, pv);
    // attention
    attn_kernel<<<dim3(BATCH, NH), 128>>>();
    // O projection (+bias)
    conv_hilo<<<(MQ * DIM / 4 + 255) / 256, 256>>>(pa, pah, pal, MQ * DIM / 4);
    gemm_mma<<<dim3(4, MQ / 128), 256, SMEMSZ>>>(pah, pal, pwh + 3 * WSZ, pwl + 3 * WSZ, bo, out);
}

// round 5
// speedup vs baseline: 2.8722x; 1.0226x over previous
#include <cuda_runtime.h>
#include <cuda_bf16.h>
#include <cstdint>

// ---------------------------------------------------------------- constants
#define DIM   512
#define NH    8
#define DH    64
#define NLAT  128
#define NTOK  16
#define BATCH 1024
#define MQ    (BATCH * NTOK)     // 16384 query rows
#define MKV_C 66048              // compacted K/V rows: 8 * 128*129/2
#define GRP_OFF 8256             // rows per 128-batch group

#define PAD   72                 // smem row stride (bf16) -> conflict-free ldmatrix

// ---------------------------------------------------------------- scratch
__device__ float g_q  [MQ    * DIM];
__device__ float g_k  [MKV_C * DIM];
__device__ float g_v  [MKV_C * DIM];

__device__ __nv_bfloat16 g_xh[MQ * DIM],    g_xl[MQ * DIM];
__device__ __nv_bfloat16 g_lh[MKV_C * DIM], g_ll[MKV_C * DIM];
__device__ __nv_bfloat16 g_ah[MQ * DIM],    g_al[MQ * DIM];
__device__ __nv_bfloat16 g_wh[4 * DIM * DIM], g_wl[4 * DIM * DIM]; // Wq|Wk|Wv|Wo

// ---------------------------------------------------------------- helpers
__device__ __forceinline__ uint32_t smem_u32(const void* p) {
    uint32_t a;
    asm("{ .reg .u64 t; cvta.to.shared.u64 t, %1; cvt.u32.u64 %0, t; }"
        : "=r"(a) : "l"(p));
    return a;
}

#define LDMX4(r0, r1, r2, r3, addr)                                          \
    asm volatile("ldmatrix.sync.aligned.m8n8.x4.shared.b16 {%0,%1,%2,%3}, [%4];" \
                 : "=r"(r0), "=r"(r1), "=r"(r2), "=r"(r3) : "r"(addr))

#define MMA16816(d, a, b0, b1)                                               \
    asm volatile("mma.sync.aligned.m16n8k16.row.col.f32.bf16.bf16.f32 "      \
                 "{%0,%1,%2,%3},{%4,%5,%6,%7},{%8,%9},{%0,%1,%2,%3};"        \
                 : "+f"((d)[0]), "+f"((d)[1]), "+f"((d)[2]), "+f"((d)[3])    \
                 : "r"((a)[0]), "r"((a)[1]), "r"((a)[2]), "r"((a)[3]),       \
                   "r"(b0), "r"(b1))

#define CP16(dst, src)                                                       \
    asm volatile("cp.async.cg.shared.global [%0], [%1], 16;"                 \
                 :: "r"(dst), "l"(src))
#define CP_COMMIT() asm volatile("cp.async.commit_group;")
#define CP_WAIT0()  asm volatile("cp.async.wait_group 0;")

// ---------------------------------------------------------------- hi/lo split
__device__ __forceinline__ void split2(float x, float y, uint32_t& hi, uint32_t& lo) {
    __nv_bfloat16 hx = __float2bfloat16(x), hy = __float2bfloat16(y);
    __nv_bfloat16 lx = __float2bfloat16(x - __bfloat162float(hx));
    __nv_bfloat16 ly = __float2bfloat16(y - __bfloat162float(hy));
    __nv_bfloat162 H = __halves2bfloat162(hx, hy);
    __nv_bfloat162 L = __halves2bfloat162(lx, ly);
    hi = *reinterpret_cast<uint32_t*>(&H);
    lo = *reinterpret_cast<uint32_t*>(&L);
}

__global__ __launch_bounds__(256) void conv_hilo(const float* __restrict__ src,
                                                 __nv_bfloat16* __restrict__ hi,
                                                 __nv_bfloat16* __restrict__ lo, int n4)
{
    int i = blockIdx.x * 256 + threadIdx.x;
    if (i >= n4) return;
    float4 v = ((const float4*)src)[i];
    uint2 H, L;
    split2(v.x, v.y, H.x, L.x);
    split2(v.z, v.w, H.y, L.y);
    ((uint2*)hi)[i] = H;
    ((uint2*)lo)[i] = L;
}

// all 4 weights in one launch: i>>16 selects weight, low 16 bits = float4 idx
__global__ __launch_bounds__(256) void conv_w(const float* __restrict__ w0,
                                              const float* __restrict__ w1,
                                              const float* __restrict__ w2,
                                              const float* __restrict__ w3)
{
    int i = blockIdx.x * 256 + threadIdx.x;      // 0 .. 4*65536-1
    int wi = i >> 16, j = i & 65535;
    const float* src = (wi == 0) ? w0 : (wi == 1) ? w1 : (wi == 2) ? w2 : w3;
    float4 v = ((const float4*)src)[j];
    uint2 H, L;
    split2(v.x, v.y, H.x, L.x);
    split2(v.z, v.w, H.y, L.y);
    ((uint2*)(g_wh + (size_t)wi * DIM * DIM))[j] = H;
    ((uint2*)(g_wl + (size_t)wi * DIM * DIM))[j] = L;
}

// gather+split live latent rows into compact layout (row = off(b)+j)
__global__ __launch_bounds__(128) void gather_l(const float* __restrict__ L)
{
    const int b = blockIdx.x, j = blockIdx.y;
    const int m = b & 127;
    if (j > m) return;
    const int r = (b >> 7) * GRP_OFF + (m * (m + 1)) / 2 + j;
    const int t = threadIdx.x;
    float4 v = ((const float4*)&L[(size_t)(b * NLAT + j) * DIM])[t];
    uint2 H, Lo;
    split2(v.x, v.y, H.x, Lo.x);
    split2(v.z, v.w, H.y, Lo.y);
    ((uint2*)&g_lh[(size_t)r * DIM])[t] = H;
    ((uint2*)&g_ll[(size_t)r * DIM])[t] = Lo;
}

// ---------------------------------------------------------------- GEMM core
// Shared body: C tile (bm,bn) of A @ W^T via 3-pass bf16 compensation.
struct GemmPtrs {
    const __nv_bfloat16 *Ah, *Al, *Wh, *Wl;
    const float* bias;
    float* C;
};

__device__ __forceinline__ void gemm_body(const GemmPtrs& P, int bm, int bn,
                                          __nv_bfloat16* sm)
{
    __nv_bfloat16* sAh = sm;
    __nv_bfloat16* sAl = sAh + 128 * PAD;
    __nv_bfloat16* sBh = sAl + 128 * PAD;
    __nv_bfloat16* sBl = sBh + 128 * PAD;

    const int t = threadIdx.x;
    const int w = t >> 5, lane = t & 31;
    const int wy = w >> 2, wx = w & 3;
    const int r8 = lane & 7, sub = lane >> 3;

    const uint32_t aAh = smem_u32(sAh), aAl = smem_u32(sAl);
    const uint32_t aBh = smem_u32(sBh), aBl = smem_u32(sBl);

    float acc[4][4][4];
#pragma unroll
    for (int mi = 0; mi < 4; mi++)
#pragma unroll
        for (int ni = 0; ni < 4; ni++)
#pragma unroll
            for (int e = 0; e < 4; e++) acc[mi][ni][e] = 0.f;

    const int grow = t >> 1;
    const int gkc  = (t & 1) * 4;
    const int aRow = (sub & 1) * 8 + r8, aCol = (sub >> 1) * 8;
    const int bRow = (sub >> 1) * 8 + r8, bCol = (sub & 1) * 8;

    for (int ch = 0; ch < 8; ch++) {
        const int kt = ch * 64;
        const __nv_bfloat16* pAh = &P.Ah[(size_t)(bm + grow) * DIM + kt + gkc * 8];
        const __nv_bfloat16* pAl = &P.Al[(size_t)(bm + grow) * DIM + kt + gkc * 8];
        const __nv_bfloat16* pWh = &P.Wh[(size_t)(bn + grow) * DIM + kt + gkc * 8];
        const __nv_bfloat16* pWl = &P.Wl[(size_t)(bn + grow) * DIM + kt + gkc * 8];
        const uint32_t soff = (uint32_t)((grow * PAD + gkc * 8) * 2);
#pragma unroll
        for (int u = 0; u < 4; u++) {
            CP16(aAh + soff + u * 16, pAh + u * 8);
            CP16(aAl + soff + u * 16, pAl + u * 8);
            CP16(aBh + soff + u * 16, pWh + u * 8);
            CP16(aBl + soff + u * 16, pWl + u * 8);
        }
        CP_COMMIT();
        CP_WAIT0();
        __syncthreads();

#pragma unroll
        for (int k16 = 0; k16 < 4; k16++) {
            const int k0 = k16 * 16;
            uint32_t ah[4][4], al[4][4];
#pragma unroll
            for (int mi = 0; mi < 4; mi++) {
                const uint32_t off = (uint32_t)(((wy * 64 + mi * 16 + aRow) * PAD + k0 + aCol) * 2);
                LDMX4(ah[mi][0], ah[mi][1], ah[mi][2], ah[mi][3], aAh + off);
                LDMX4(al[mi][0], al[mi][1], al[mi][2], al[mi][3], aAl + off);
            }
            uint32_t bh[8], bl[8];
#pragma unroll
            for (int p = 0; p < 2; p++) {
                const uint32_t off = (uint32_t)(((wx * 32 + p * 16 + bRow) * PAD + k0 + bCol) * 2);
                LDMX4(bh[p * 4 + 0], bh[p * 4 + 1], bh[p * 4 + 2], bh[p * 4 + 3], aBh + off);
                LDMX4(bl[p * 4 + 0], bl[p * 4 + 1], bl[p * 4 + 2], bl[p * 4 + 3], aBl + off);
            }
#pragma unroll
            for (int mi = 0; mi < 4; mi++)
#pragma unroll
                for (int ni = 0; ni < 4; ni++) {
                    MMA16816(acc[mi][ni], ah[mi], bh[ni * 2], bh[ni * 2 + 1]);
                    MMA16816(acc[mi][ni], ah[mi], bl[ni * 2], bl[ni * 2 + 1]);
                    MMA16816(acc[mi][ni], al[mi], bh[ni * 2], bh[ni * 2 + 1]);
                }
        }
        __syncthreads();
    }

    const int g = lane >> 2, tg = lane & 3;
#pragma unroll
    for (int mi = 0; mi < 4; mi++) {
        const int row0 = bm + wy * 64 + mi * 16 + g;
#pragma unroll
        for (int ni = 0; ni < 4; ni++) {
            const int col = bn + wx * 32 + ni * 8 + tg * 2;
            float b0 = 0.f, b1 = 0.f;
            if (P.bias) { b0 = P.bias[col]; b1 = P.bias[col + 1]; }
            *(float2*)&P.C[(size_t)row0 * DIM + col] =
                make_float2(acc[mi][ni][0] + b0, acc[mi][ni][1] + b1);
            *(float2*)&P.C[(size_t)(row0 + 8) * DIM + col] =
                make_float2(acc[mi][ni][2] + b0, acc[mi][ni][3] + b1);
        }
    }
}

// Q / O projections: grid (4, M/128)
__global__ __launch_bounds__(256, 2) void gemm_mma(
    const __nv_bfloat16* __restrict__ Ah, const __nv_bfloat16* __restrict__ Al,
    const __nv_bfloat16* __restrict__ Wh, const __nv_bfloat16* __restrict__ Wl,
    const float* __restrict__ bias, float* __restrict__ C)
{
    extern __shared__ __nv_bfloat16 sm[];
    GemmPtrs P{Ah, Al, Wh, Wl, bias, C};
    gemm_body(P, blockIdx.y * 128, blockIdx.x * 128, sm);
}

// Fused K+V projection: grid (8, MKV_C/128); x<4 -> K slab, else V slab.
// Co-resident CTAs with same blockIdx.y share the A tile via L2.
__global__ __launch_bounds__(256, 2) void gemm_kv(
    const __nv_bfloat16* __restrict__ Ah, const __nv_bfloat16* __restrict__ Al,
    const __nv_bfloat16* __restrict__ Wkh, const __nv_bfloat16* __restrict__ Wkl,
    const __nv_bfloat16* __restrict__ Wvh, const __nv_bfloat16* __restrict__ Wvl,
    float* __restrict__ K, float* __restrict__ V)
{
    extern __shared__ __nv_bfloat16 sm[];
    const int bnv = blockIdx.x * 128;
    GemmPtrs P;
    P.Ah = Ah; P.Al = Al; P.bias = nullptr;
    int bn;
    if (bnv < 512) { P.Wh = Wkh; P.Wl = Wkl; P.C = K; bn = bnv; }
    else           { P.Wh = Wvh; P.Wl = Wvl; P.C = V; bn = bnv - 512; }
    gemm_body(P, blockIdx.y * 128, bn, sm);
}

// ---------------------------------------------------------------- attention
// One block per (b,h); writes bf16 hi/lo directly (O-proj input).
__global__ __launch_bounds__(128) void attn_kernel()
{
    const int b = blockIdx.x;
    const int h = blockIdx.y;
    const int t = threadIdx.x;
    const int m = b & 127;
    const int nj = m + 1;
    const size_t kvbase = (size_t)((b >> 7) * GRP_OFF + (m * (m + 1)) / 2);

    __shared__ float qs[NTOK][DH + 1];
    __shared__ float ps[NTOK][NLAT + 1];

#pragma unroll
    for (int u = 0; u < 8; u++) {
        int e = t + u * 128;
        qs[e >> 6][e & 63] = g_q[(size_t)(b * NTOK + (e >> 6)) * DIM + h * DH + (e & 63)];
    }
    __syncthreads();

    {
        const int i = t & 15;
        const int jg = t >> 4;
        for (int j = jg; j < nj; j += 8) {
            const float4* k4 = (const float4*)&g_k[(kvbase + j) * DIM + h * DH];
            float s = 0.f;
#pragma unroll
            for (int d4 = 0; d4 < 16; d4++) {
                float4 kk = k4[d4];
                s += qs[i][d4 * 4 + 0] * kk.x + qs[i][d4 * 4 + 1] * kk.y
                   + qs[i][d4 * 4 + 2] * kk.z + qs[i][d4 * 4 + 3] * kk.w;
            }
            ps[i][j] = s * 0.125f;
        }
    }
    __syncthreads();

    if (t < NTOK) {
        float mx = -1e30f;
        for (int j = 0; j < nj; j++) mx = fmaxf(mx, ps[t][j]);
        float s = 0.f;
        for (int j = 0; j < nj; j++) { float e = expf(ps[t][j] - mx); ps[t][j] = e; s += e; }
        float inv = 1.f / s;
        for (int j = 0; j < nj; j++) ps[t][j] *= inv;
    }
    __syncthreads();

    {
        const int d  = t & 63;
        const int i0 = t >> 6;
        float acc[8];
#pragma unroll
        for (int ii = 0; ii < 8; ii++) acc[ii] = 0.f;
        for (int j = 0; j < nj; j++) {
            float vv = g_v[(kvbase + j) * DIM + h * DH + d];
#pragma unroll
            for (int ii = 0; ii < 8; ii++)
                acc[ii] += ps[i0 + 2 * ii][j] * vv;
        }
#pragma unroll
        for (int ii = 0; ii < 8; ii++) {
            size_t idx = (size_t)(b * NTOK + i0 + 2 * ii) * DIM + h * DH + d;
            __nv_bfloat16 hv = __float2bfloat16(acc[ii]);
            g_ah[idx] = hv;
            g_al[idx] = __float2bfloat16(acc[ii] - __bfloat162float(hv));
        }
    }
}

// ---------------------------------------------------------------- launch
extern "C" void kernel_launch(void* const* d_in, const int* in_sizes, int n_in,
                              void* d_out, int out_size)
{
    const float* x  = (const float*)d_in[0];
    const float* l  = (const float*)d_in[1];
    const float* Wq = (const float*)d_in[2];
    const float* Wk = (const float*)d_in[3];
    const float* Wv = (const float*)d_in[4];
    const float* Wo = (const float*)d_in[5];
    const float* bo = (const float*)d_in[6];
    float* out = (float*)d_out;

    float *pq, *pk, *pv;
    __nv_bfloat16 *pxh, *pxl, *pah, *pal, *pwh, *pwl, *plh, *pll;
    cudaGetSymbolAddress((void**)&pq,  g_q);
    cudaGetSymbolAddress((void**)&pk,  g_k);
    cudaGetSymbolAddress((void**)&pv,  g_v);
    cudaGetSymbolAddress((void**)&pxh, g_xh);
    cudaGetSymbolAddress((void**)&pxl, g_xl);
    cudaGetSymbolAddress((void**)&pah, g_ah);
    cudaGetSymbolAddress((void**)&pal, g_al);
    cudaGetSymbolAddress((void**)&pwh, g_wh);
    cudaGetSymbolAddress((void**)&pwl, g_wl);
    cudaGetSymbolAddress((void**)&plh, g_lh);
    cudaGetSymbolAddress((void**)&pll, g_ll);

    const int SMEMSZ = 4 * 128 * PAD * 2;        // 73728 B
    cudaFuncSetAttribute(gemm_mma, cudaFuncAttributeMaxDynamicSharedMemorySize, SMEMSZ);
    cudaFuncSetAttribute(gemm_kv,  cudaFuncAttributeMaxDynamicSharedMemorySize, SMEMSZ);

    const int WSZ = DIM * DIM;

    // prep: hi/lo splits
    conv_hilo<<<(MQ * DIM / 4 + 255) / 256, 256>>>(x, pxh, pxl, MQ * DIM / 4);
    conv_w<<<4 * WSZ / 4 / 256, 256>>>(Wq, Wk, Wv, Wo);
    gather_l<<<dim3(BATCH, NLAT), 128>>>(l);

    // Q projection
    gemm_mma<<<dim3(4, MQ / 128), 256, SMEMSZ>>>(pxh, pxl, pwh + 0 * WSZ, pwl + 0 * WSZ, nullptr, pq);
    // fused K+V projection on compact rows (L2-shared A tiles)
    gemm_kv<<<dim3(8, MKV_C / 128), 256, SMEMSZ>>>(plh, pll,
                                                   pwh + 1 * WSZ, pwl + 1 * WSZ,
                                                   pwh + 2 * WSZ, pwl + 2 * WSZ, pk, pv);
    // attention (writes bf16 hi/lo for O-proj directly)
    attn_kernel<<<dim3(BATCH, NH), 128>>>();
    // O projection (+bias)
    gemm_mma<<<dim3(4, MQ / 128), 256, SMEMSZ>>>(pah, pal, pwh + 3 * WSZ, pwl + 3 * WSZ, bo, out);
}

// round 6
// speedup vs baseline: 3.0728x; 1.0699x over previous
#include <cuda_runtime.h>
#include <cuda_bf16.h>
#include <cstdint>

// ---------------------------------------------------------------- constants
#define DIM   512
#define NH    8
#define DH    64
#define NLAT  128
#define NTOK  16
#define BATCH 1024
#define MQ    (BATCH * NTOK)     // 16384 query rows
#define MKV_C 66048              // compacted K/V rows: 8 * 128*129/2
#define GRP_OFF 8256             // rows per 128-batch group

#define KB    32                 // k-chunk
#define PADE  40                 // smem row stride in bf16 elems (80B, conflict-free)
#define BUFE  (128 * PADE)       // one buffer, elems
#define STAGE_E (4 * BUFE)       // Ah|Al|Bh|Bl, elems
#define SMEMSZ (2 * STAGE_E * 2) // bytes: 2 stages

// ---------------------------------------------------------------- scratch
__device__ float g_q  [MQ    * DIM];
__device__ float g_k  [MKV_C * DIM];
__device__ float g_v  [MKV_C * DIM];

__device__ __nv_bfloat16 g_xh[MQ * DIM],    g_xl[MQ * DIM];
__device__ __nv_bfloat16 g_lh[MKV_C * DIM], g_ll[MKV_C * DIM];
__device__ __nv_bfloat16 g_ah[MQ * DIM],    g_al[MQ * DIM];
__device__ __nv_bfloat16 g_wh[4 * DIM * DIM], g_wl[4 * DIM * DIM]; // Wq|Wk|Wv|Wo

// ---------------------------------------------------------------- helpers
__device__ __forceinline__ uint32_t smem_u32(const void* p) {
    uint32_t a;
    asm("{ .reg .u64 t; cvta.to.shared.u64 t, %1; cvt.u32.u64 %0, t; }"
        : "=r"(a) : "l"(p));
    return a;
}

#define LDMX4(r0, r1, r2, r3, addr)                                          \
    asm volatile("ldmatrix.sync.aligned.m8n8.x4.shared.b16 {%0,%1,%2,%3}, [%4];" \
                 : "=r"(r0), "=r"(r1), "=r"(r2), "=r"(r3) : "r"(addr))

#define MMA16816(d, a, b0, b1)                                               \
    asm volatile("mma.sync.aligned.m16n8k16.row.col.f32.bf16.bf16.f32 "      \
                 "{%0,%1,%2,%3},{%4,%5,%6,%7},{%8,%9},{%0,%1,%2,%3};"        \
                 : "+f"((d)[0]), "+f"((d)[1]), "+f"((d)[2]), "+f"((d)[3])    \
                 : "r"((a)[0]), "r"((a)[1]), "r"((a)[2]), "r"((a)[3]),       \
                   "r"(b0), "r"(b1))

#define CP16(dst, src)                                                       \
    asm volatile("cp.async.cg.shared.global [%0], [%1], 16;"                 \
                 :: "r"(dst), "l"(src))
#define CP_COMMIT()  asm volatile("cp.async.commit_group;")
#define CP_WAIT(n)   asm volatile("cp.async.wait_group %0;" :: "n"(n))

// ---------------------------------------------------------------- hi/lo split
__device__ __forceinline__ void split2(float x, float y, uint32_t& hi, uint32_t& lo) {
    __nv_bfloat16 hx = __float2bfloat16(x), hy = __float2bfloat16(y);
    __nv_bfloat16 lx = __float2bfloat16(x - __bfloat162float(hx));
    __nv_bfloat16 ly = __float2bfloat16(y - __bfloat162float(hy));
    __nv_bfloat162 H = __halves2bfloat162(hx, hy);
    __nv_bfloat162 L = __halves2bfloat162(lx, ly);
    hi = *reinterpret_cast<uint32_t*>(&H);
    lo = *reinterpret_cast<uint32_t*>(&L);
}

__global__ __launch_bounds__(256) void conv_hilo(const float* __restrict__ src,
                                                 __nv_bfloat16* __restrict__ hi,
                                                 __nv_bfloat16* __restrict__ lo, int n4)
{
    int i = blockIdx.x * 256 + threadIdx.x;
    if (i >= n4) return;
    float4 v = ((const float4*)src)[i];
    uint2 H, L;
    split2(v.x, v.y, H.x, L.x);
    split2(v.z, v.w, H.y, L.y);
    ((uint2*)hi)[i] = H;
    ((uint2*)lo)[i] = L;
}

__global__ __launch_bounds__(256) void conv_w(const float* __restrict__ w0,
                                              const float* __restrict__ w1,
                                              const float* __restrict__ w2,
                                              const float* __restrict__ w3)
{
    int i = blockIdx.x * 256 + threadIdx.x;
    int wi = i >> 16, j = i & 65535;
    const float* src = (wi == 0) ? w0 : (wi == 1) ? w1 : (wi == 2) ? w2 : w3;
    float4 v = ((const float4*)src)[j];
    uint2 H, L;
    split2(v.x, v.y, H.x, L.x);
    split2(v.z, v.w, H.y, L.y);
    ((uint2*)(g_wh + (size_t)wi * DIM * DIM))[j] = H;
    ((uint2*)(g_wl + (size_t)wi * DIM * DIM))[j] = L;
}

__global__ __launch_bounds__(128) void gather_l(const float* __restrict__ L)
{
    const int b = blockIdx.x, j = blockIdx.y;
    const int m = b & 127;
    if (j > m) return;
    const int r = (b >> 7) * GRP_OFF + (m * (m + 1)) / 2 + j;
    const int t = threadIdx.x;
    float4 v = ((const float4*)&L[(size_t)(b * NLAT + j) * DIM])[t];
    uint2 H, Lo;
    split2(v.x, v.y, H.x, Lo.x);
    split2(v.z, v.w, H.y, Lo.y);
    ((uint2*)&g_lh[(size_t)r * DIM])[t] = H;
    ((uint2*)&g_ll[(size_t)r * DIM])[t] = Lo;
}

// ---------------------------------------------------------------- GEMM core
struct GemmPtrs {
    const __nv_bfloat16 *Ah, *Al, *Wh, *Wl;
    const float* bias;
    float* C;
};

__device__ __forceinline__ void gemm_body(const GemmPtrs& P, int bm, int bn,
                                          __nv_bfloat16* sm)
{
    const int t = threadIdx.x;
    const int w = t >> 5, lane = t & 31;
    const int wy = w >> 2, wx = w & 3;        // warp tile (wy*64, wx*32)
    const int r8 = lane & 7, sub = lane >> 3;

    const uint32_t sbase = smem_u32(sm);

    float acc[4][4][4];
#pragma unroll
    for (int mi = 0; mi < 4; mi++)
#pragma unroll
        for (int ni = 0; ni < 4; ni++)
#pragma unroll
            for (int e = 0; e < 4; e++) acc[mi][ni][e] = 0.f;

    // staging: thread -> row t>>1, col half (t&1)*16 (two CP16 per buffer)
    const int grow = t >> 1;
    const int gc   = (t & 1) * 16;
    const uint32_t soff = (uint32_t)((grow * PADE + gc) * 2);

    const int aRow = (sub & 1) * 8 + r8, aCol = (sub >> 1) * 8;
    const int bRow = (sub >> 1) * 8 + r8, bCol = (sub & 1) * 8;

    const int NCH = DIM / KB;   // 16

    // issue loads for chunk ch into stage s
    auto load_chunk = [&](int ch, int s) {
        const int kt = ch * KB;
        const uint32_t st = sbase + (uint32_t)(s * STAGE_E * 2);
        const __nv_bfloat16* pAh = &P.Ah[(size_t)(bm + grow) * DIM + kt + gc];
        const __nv_bfloat16* pAl = &P.Al[(size_t)(bm + grow) * DIM + kt + gc];
        const __nv_bfloat16* pWh = &P.Wh[(size_t)(bn + grow) * DIM + kt + gc];
        const __nv_bfloat16* pWl = &P.Wl[(size_t)(bn + grow) * DIM + kt + gc];
        CP16(st + 0 * BUFE * 2 + soff,      pAh);
        CP16(st + 0 * BUFE * 2 + soff + 16, pAh + 8);
        CP16(st + 1 * BUFE * 2 + soff,      pAl);
        CP16(st + 1 * BUFE * 2 + soff + 16, pAl + 8);
        CP16(st + 2 * BUFE * 2 + soff,      pWh);
        CP16(st + 2 * BUFE * 2 + soff + 16, pWh + 8);
        CP16(st + 3 * BUFE * 2 + soff,      pWl);
        CP16(st + 3 * BUFE * 2 + soff + 16, pWl + 8);
        CP_COMMIT();
    };

    load_chunk(0, 0);

    for (int ch = 0; ch < NCH; ch++) {
        const int s = ch & 1;
        if (ch + 1 < NCH) load_chunk(ch + 1, s ^ 1);

        if (ch + 1 < NCH) CP_WAIT(1); else CP_WAIT(0);
        __syncthreads();

        const uint32_t st = sbase + (uint32_t)(s * STAGE_E * 2);
        const uint32_t aAh = st;
        const uint32_t aAl = st + 1 * BUFE * 2;
        const uint32_t aBh = st + 2 * BUFE * 2;
        const uint32_t aBl = st + 3 * BUFE * 2;

#pragma unroll
        for (int k16 = 0; k16 < KB / 16; k16++) {
            const int k0 = k16 * 16;
            uint32_t ah[4][4], al[4][4];
#pragma unroll
            for (int mi = 0; mi < 4; mi++) {
                const uint32_t off = (uint32_t)(((wy * 64 + mi * 16 + aRow) * PADE + k0 + aCol) * 2);
                LDMX4(ah[mi][0], ah[mi][1], ah[mi][2], ah[mi][3], aAh + off);
                LDMX4(al[mi][0], al[mi][1], al[mi][2], al[mi][3], aAl + off);
            }
            uint32_t bh[8], bl[8];
#pragma unroll
            for (int p = 0; p < 2; p++) {
                const uint32_t off = (uint32_t)(((wx * 32 + p * 16 + bRow) * PADE + k0 + bCol) * 2);
                LDMX4(bh[p * 4 + 0], bh[p * 4 + 1], bh[p * 4 + 2], bh[p * 4 + 3], aBh + off);
                LDMX4(bl[p * 4 + 0], bl[p * 4 + 1], bl[p * 4 + 2], bl[p * 4 + 3], aBl + off);
            }
#pragma unroll
            for (int mi = 0; mi < 4; mi++)
#pragma unroll
                for (int ni = 0; ni < 4; ni++) {
                    MMA16816(acc[mi][ni], ah[mi], bh[ni * 2], bh[ni * 2 + 1]);
                    MMA16816(acc[mi][ni], ah[mi], bl[ni * 2], bl[ni * 2 + 1]);
                    MMA16816(acc[mi][ni], al[mi], bh[ni * 2], bh[ni * 2 + 1]);
                }
        }
        __syncthreads();
    }

    const int g = lane >> 2, tg = lane & 3;
#pragma unroll
    for (int mi = 0; mi < 4; mi++) {
        const int row0 = bm + wy * 64 + mi * 16 + g;
#pragma unroll
        for (int ni = 0; ni < 4; ni++) {
            const int col = bn + wx * 32 + ni * 8 + tg * 2;
            float b0 = 0.f, b1 = 0.f;
            if (P.bias) { b0 = P.bias[col]; b1 = P.bias[col + 1]; }
            *(float2*)&P.C[(size_t)row0 * DIM + col] =
                make_float2(acc[mi][ni][0] + b0, acc[mi][ni][1] + b1);
            *(float2*)&P.C[(size_t)(row0 + 8) * DIM + col] =
                make_float2(acc[mi][ni][2] + b0, acc[mi][ni][3] + b1);
        }
    }
}

__global__ __launch_bounds__(256, 2) void gemm_mma(
    const __nv_bfloat16* __restrict__ Ah, const __nv_bfloat16* __restrict__ Al,
    const __nv_bfloat16* __restrict__ Wh, const __nv_bfloat16* __restrict__ Wl,
    const float* __restrict__ bias, float* __restrict__ C)
{
    extern __shared__ __nv_bfloat16 sm[];
    GemmPtrs P{Ah, Al, Wh, Wl, bias, C};
    gemm_body(P, blockIdx.y * 128, blockIdx.x * 128, sm);
}

__global__ __launch_bounds__(256, 2) void gemm_kv(
    const __nv_bfloat16* __restrict__ Ah, const __nv_bfloat16* __restrict__ Al,
    const __nv_bfloat16* __restrict__ Wkh, const __nv_bfloat16* __restrict__ Wkl,
    const __nv_bfloat16* __restrict__ Wvh, const __nv_bfloat16* __restrict__ Wvl,
    float* __restrict__ K, float* __restrict__ V)
{
    extern __shared__ __nv_bfloat16 sm[];
    const int bnv = blockIdx.x * 128;
    GemmPtrs P;
    P.Ah = Ah; P.Al = Al; P.bias = nullptr;
    int bn;
    if (bnv < 512) { P.Wh = Wkh; P.Wl = Wkl; P.C = K; bn = bnv; }
    else           { P.Wh = Wvh; P.Wl = Wvl; P.C = V; bn = bnv - 512; }
    gemm_body(P, blockIdx.y * 128, bn, sm);
}

// ---------------------------------------------------------------- attention
__global__ __launch_bounds__(128) void attn_kernel()
{
    const int b = blockIdx.x;
    const int h = blockIdx.y;
    const int t = threadIdx.x;
    const int m = b & 127;
    const int nj = m + 1;
    const size_t kvbase = (size_t)((b >> 7) * GRP_OFF + (m * (m + 1)) / 2);

    __shared__ float qs[NTOK][DH + 1];
    __shared__ float ps[NTOK][NLAT + 1];

#pragma unroll
    for (int u = 0; u < 8; u++) {
        int e = t + u * 128;
        qs[e >> 6][e & 63] = g_q[(size_t)(b * NTOK + (e >> 6)) * DIM + h * DH + (e & 63)];
    }
    __syncthreads();

    {
        const int i = t & 15;
        const int jg = t >> 4;
        for (int j = jg; j < nj; j += 8) {
            const float4* k4 = (const float4*)&g_k[(kvbase + j) * DIM + h * DH];
            float s = 0.f;
#pragma unroll
            for (int d4 = 0; d4 < 16; d4++) {
                float4 kk = k4[d4];
                s += qs[i][d4 * 4 + 0] * kk.x + qs[i][d4 * 4 + 1] * kk.y
                   + qs[i][d4 * 4 + 2] * kk.z + qs[i][d4 * 4 + 3] * kk.w;
            }
            ps[i][j] = s * 0.125f;
        }
    }
    __syncthreads();

    if (t < NTOK) {
        float mx = -1e30f;
        for (int j = 0; j < nj; j++) mx = fmaxf(mx, ps[t][j]);
        float s = 0.f;
        for (int j = 0; j < nj; j++) { float e = expf(ps[t][j] - mx); ps[t][j] = e; s += e; }
        float inv = 1.f / s;
        for (int j = 0; j < nj; j++) ps[t][j] *= inv;
    }
    __syncthreads();

    {
        const int d  = t & 63;
        const int i0 = t >> 6;
        float acc[8];
#pragma unroll
        for (int ii = 0; ii < 8; ii++) acc[ii] = 0.f;
        for (int j = 0; j < nj; j++) {
            float vv = g_v[(kvbase + j) * DIM + h * DH + d];
#pragma unroll
            for (int ii = 0; ii < 8; ii++)
                acc[ii] += ps[i0 + 2 * ii][j] * vv;
        }
#pragma unroll
        for (int ii = 0; ii < 8; ii++) {
            size_t idx = (size_t)(b * NTOK + i0 + 2 * ii) * DIM + h * DH + d;
            __nv_bfloat16 hv = __float2bfloat16(acc[ii]);
            g_ah[idx] = hv;
            g_al[idx] = __float2bfloat16(acc[ii] - __bfloat162float(hv));
        }
    }
}

// ---------------------------------------------------------------- launch
extern "C" void kernel_launch(void* const* d_in, const int* in_sizes, int n_in,
                              void* d_out, int out_size)
{
    const float* x  = (const float*)d_in[0];
    const float* l  = (const float*)d_in[1];
    const float* Wq = (const float*)d_in[2];
    const float* Wk = (const float*)d_in[3];
    const float* Wv = (const float*)d_in[4];
    const float* Wo = (const float*)d_in[5];
    const float* bo = (const float*)d_in[6];
    float* out = (float*)d_out;

    float *pq, *pk, *pv;
    __nv_bfloat16 *pxh, *pxl, *pah, *pal, *pwh, *pwl, *plh, *pll;
    cudaGetSymbolAddress((void**)&pq,  g_q);
    cudaGetSymbolAddress((void**)&pk,  g_k);
    cudaGetSymbolAddress((void**)&pv,  g_v);
    cudaGetSymbolAddress((void**)&pxh, g_xh);
    cudaGetSymbolAddress((void**)&pxl, g_xl);
    cudaGetSymbolAddress((void**)&pah, g_ah);
    cudaGetSymbolAddress((void**)&pal, g_al);
    cudaGetSymbolAddress((void**)&pwh, g_wh);
    cudaGetSymbolAddress((void**)&pwl, g_wl);
    cudaGetSymbolAddress((void**)&plh, g_lh);
    cudaGetSymbolAddress((void**)&pll, g_ll);

    cudaFuncSetAttribute(gemm_mma, cudaFuncAttributeMaxDynamicSharedMemorySize, SMEMSZ);
    cudaFuncSetAttribute(gemm_kv,  cudaFuncAttributeMaxDynamicSharedMemorySize, SMEMSZ);

    const int WSZ = DIM * DIM;

    conv_hilo<<<(MQ * DIM / 4 + 255) / 256, 256>>>(x, pxh, pxl, MQ * DIM / 4);
    conv_w<<<4 * WSZ / 4 / 256, 256>>>(Wq, Wk, Wv, Wo);
    gather_l<<<dim3(BATCH, NLAT), 128>>>(l);

    gemm_mma<<<dim3(4, MQ / 128), 256, SMEMSZ>>>(pxh, pxl, pwh + 0 * WSZ, pwl + 0 * WSZ, nullptr, pq);
    gemm_kv<<<dim3(8, MKV_C / 128), 256, SMEMSZ>>>(plh, pll,
                                                   pwh + 1 * WSZ, pwl + 1 * WSZ,
                                                   pwh + 2 * WSZ, pwl + 2 * WSZ, pk, pv);
    attn_kernel<<<dim3(BATCH, NH), 128>>>();
    gemm_mma<<<dim3(4, MQ / 128), 256, SMEMSZ>>>(pah, pal, pwh + 3 * WSZ, pwl + 3 * WSZ, bo, out);
}

// round 7
// speedup vs baseline: 3.1032x; 1.0099x over previous
#include <cuda_runtime.h>
#include <cuda_bf16.h>
#include <cstdint>

// ---------------------------------------------------------------- constants
#define DIM   512
#define NH    8
#define DH    64
#define NLAT  128
#define NTOK  16
#define BATCH 1024
#define MQ    (BATCH * NTOK)     // 16384 query rows
#define MKV_C 66048              // compacted K/V rows: 8 * 128*129/2
#define GRP_OFF 8256             // rows per 128-batch group

#define KB    32                 // k-chunk
#define PADE  40                 // smem row stride in bf16 elems (80B, conflict-free)
#define BUFE  (128 * PADE)       // one buffer, elems
#define STAGE_E (4 * BUFE)       // Ah|Al|Bh|Bl, elems
#define SMEMSZ (2 * STAGE_E * 2) // bytes: 2 stages

// ---------------------------------------------------------------- scratch
__device__ float g_q  [MQ    * DIM];
__device__ float g_k  [MKV_C * DIM];
__device__ float g_v  [MKV_C * DIM];

__device__ __nv_bfloat16 g_xh[MQ * DIM],    g_xl[MQ * DIM];
__device__ __nv_bfloat16 g_lh[MKV_C * DIM], g_ll[MKV_C * DIM];
__device__ __nv_bfloat16 g_ah[MQ * DIM],    g_al[MQ * DIM];
__device__ __nv_bfloat16 g_wh[4 * DIM * DIM], g_wl[4 * DIM * DIM]; // Wq|Wk|Wv|Wo

// ---------------------------------------------------------------- helpers
__device__ __forceinline__ uint32_t smem_u32(const void* p) {
    uint32_t a;
    asm("{ .reg .u64 t; cvta.to.shared.u64 t, %1; cvt.u32.u64 %0, t; }"
        : "=r"(a) : "l"(p));
    return a;
}

#define LDMX4(r0, r1, r2, r3, addr)                                          \
    asm volatile("ldmatrix.sync.aligned.m8n8.x4.shared.b16 {%0,%1,%2,%3}, [%4];" \
                 : "=r"(r0), "=r"(r1), "=r"(r2), "=r"(r3) : "r"(addr))

// NOTE: non-volatile — lets ptxas schedule MMAs around each other / ldmatrix.
#define MMA16816(d, a, b0, b1)                                               \
    asm("mma.sync.aligned.m16n8k16.row.col.f32.bf16.bf16.f32 "               \
        "{%0,%1,%2,%3},{%4,%5,%6,%7},{%8,%9},{%0,%1,%2,%3};"                 \
        : "+f"((d)[0]), "+f"((d)[1]), "+f"((d)[2]), "+f"((d)[3])             \
        : "r"((a)[0]), "r"((a)[1]), "r"((a)[2]), "r"((a)[3]),                \
          "r"(b0), "r"(b1))

#define CP16(dst, src)                                                       \
    asm volatile("cp.async.cg.shared.global [%0], [%1], 16;"                 \
                 :: "r"(dst), "l"(src))
#define CP_COMMIT()  asm volatile("cp.async.commit_group;")
#define CP_WAIT(n)   asm volatile("cp.async.wait_group %0;" :: "n"(n))

// ---------------------------------------------------------------- hi/lo split
__device__ __forceinline__ void split2(float x, float y, uint32_t& hi, uint32_t& lo) {
    __nv_bfloat16 hx = __float2bfloat16(x), hy = __float2bfloat16(y);
    __nv_bfloat16 lx = __float2bfloat16(x - __bfloat162float(hx));
    __nv_bfloat16 ly = __float2bfloat16(y - __bfloat162float(hy));
    __nv_bfloat162 H = __halves2bfloat162(hx, hy);
    __nv_bfloat162 L = __halves2bfloat162(lx, ly);
    hi = *reinterpret_cast<uint32_t*>(&H);
    lo = *reinterpret_cast<uint32_t*>(&L);
}

__global__ __launch_bounds__(256) void conv_hilo(const float* __restrict__ src,
                                                 __nv_bfloat16* __restrict__ hi,
                                                 __nv_bfloat16* __restrict__ lo, int n4)
{
    int i = blockIdx.x * 256 + threadIdx.x;
    if (i >= n4) return;
    float4 v = ((const float4*)src)[i];
    uint2 H, L;
    split2(v.x, v.y, H.x, L.x);
    split2(v.z, v.w, H.y, L.y);
    ((uint2*)hi)[i] = H;
    ((uint2*)lo)[i] = L;
}

__global__ __launch_bounds__(256) void conv_w(const float* __restrict__ w0,
                                              const float* __restrict__ w1,
                                              const float* __restrict__ w2,
                                              const float* __restrict__ w3)
{
    int i = blockIdx.x * 256 + threadIdx.x;
    int wi = i >> 16, j = i & 65535;
    const float* src = (wi == 0) ? w0 : (wi == 1) ? w1 : (wi == 2) ? w2 : w3;
    float4 v = ((const float4*)src)[j];
    uint2 H, L;
    split2(v.x, v.y, H.x, L.x);
    split2(v.z, v.w, H.y, L.y);
    ((uint2*)(g_wh + (size_t)wi * DIM * DIM))[j] = H;
    ((uint2*)(g_wl + (size_t)wi * DIM * DIM))[j] = L;
}

__global__ __launch_bounds__(128) void gather_l(const float* __restrict__ L)
{
    const int b = blockIdx.x, j = blockIdx.y;
    const int m = b & 127;
    if (j > m) return;
    const int r = (b >> 7) * GRP_OFF + (m * (m + 1)) / 2 + j;
    const int t = threadIdx.x;
    float4 v = ((const float4*)&L[(size_t)(b * NLAT + j) * DIM])[t];
    uint2 H, Lo;
    split2(v.x, v.y, H.x, Lo.x);
    split2(v.z, v.w, H.y, Lo.y);
    ((uint2*)&g_lh[(size_t)r * DIM])[t] = H;
    ((uint2*)&g_ll[(size_t)r * DIM])[t] = Lo;
}

// ---------------------------------------------------------------- GEMM core
struct GemmPtrs {
    const __nv_bfloat16 *Ah, *Al, *Wh, *Wl;
    const float* bias;
    float* C;
};

__device__ __forceinline__ void gemm_body(const GemmPtrs& P, int bm, int bn,
                                          __nv_bfloat16* sm)
{
    const int t = threadIdx.x;
    const int w = t >> 5, lane = t & 31;
    const int wy = w >> 2, wx = w & 3;        // warp tile (wy*64, wx*32)
    const int r8 = lane & 7, sub = lane >> 3;

    const uint32_t sbase = smem_u32(sm);

    float acc[4][4][4];
#pragma unroll
    for (int mi = 0; mi < 4; mi++)
#pragma unroll
        for (int ni = 0; ni < 4; ni++)
#pragma unroll
            for (int e = 0; e < 4; e++) acc[mi][ni][e] = 0.f;

    const int grow = t >> 1;
    const int gc   = (t & 1) * 16;
    const uint32_t soff = (uint32_t)((grow * PADE + gc) * 2);

    const int aRow = (sub & 1) * 8 + r8, aCol = (sub >> 1) * 8;
    const int bRow = (sub >> 1) * 8 + r8, bCol = (sub & 1) * 8;

    const int NCH = DIM / KB;   // 16

    auto load_chunk = [&](int ch, int s) {
        const int kt = ch * KB;
        const uint32_t st = sbase + (uint32_t)(s * STAGE_E * 2);
        const __nv_bfloat16* pAh = &P.Ah[(size_t)(bm + grow) * DIM + kt + gc];
        const __nv_bfloat16* pAl = &P.Al[(size_t)(bm + grow) * DIM + kt + gc];
        const __nv_bfloat16* pWh = &P.Wh[(size_t)(bn + grow) * DIM + kt + gc];
        const __nv_bfloat16* pWl = &P.Wl[(size_t)(bn + grow) * DIM + kt + gc];
        CP16(st + 0 * BUFE * 2 + soff,      pAh);
        CP16(st + 0 * BUFE * 2 + soff + 16, pAh + 8);
        CP16(st + 1 * BUFE * 2 + soff,      pAl);
        CP16(st + 1 * BUFE * 2 + soff + 16, pAl + 8);
        CP16(st + 2 * BUFE * 2 + soff,      pWh);
        CP16(st + 2 * BUFE * 2 + soff + 16, pWh + 8);
        CP16(st + 3 * BUFE * 2 + soff,      pWl);
        CP16(st + 3 * BUFE * 2 + soff + 16, pWl + 8);
        CP_COMMIT();
    };

    load_chunk(0, 0);

    for (int ch = 0; ch < NCH; ch++) {
        const int s = ch & 1;
        if (ch + 1 < NCH) load_chunk(ch + 1, s ^ 1);

        if (ch + 1 < NCH) CP_WAIT(1); else CP_WAIT(0);
        __syncthreads();

        const uint32_t st = sbase + (uint32_t)(s * STAGE_E * 2);
        const uint32_t aAh = st;
        const uint32_t aAl = st + 1 * BUFE * 2;
        const uint32_t aBh = st + 2 * BUFE * 2;
        const uint32_t aBl = st + 3 * BUFE * 2;

#pragma unroll
        for (int k16 = 0; k16 < KB / 16; k16++) {
            const int k0 = k16 * 16;
            // B fragments first (consumed by every pass)
            uint32_t bh[8], bl[8];
#pragma unroll
            for (int p = 0; p < 2; p++) {
                const uint32_t off = (uint32_t)(((wx * 32 + p * 16 + bRow) * PADE + k0 + bCol) * 2);
                LDMX4(bh[p * 4 + 0], bh[p * 4 + 1], bh[p * 4 + 2], bh[p * 4 + 3], aBh + off);
                LDMX4(bl[p * 4 + 0], bl[p * 4 + 1], bl[p * 4 + 2], bl[p * 4 + 3], aBl + off);
            }
            uint32_t ah[4][4], al[4][4];
#pragma unroll
            for (int mi = 0; mi < 4; mi++) {
                const uint32_t off = (uint32_t)(((wy * 64 + mi * 16 + aRow) * PADE + k0 + aCol) * 2);
                LDMX4(ah[mi][0], ah[mi][1], ah[mi][2], ah[mi][3], aAh + off);
                LDMX4(al[mi][0], al[mi][1], al[mi][2], al[mi][3], aAl + off);
            }
            // pass-outer ordering: 16 independent accumulators between
            // successive writes to the same acc -> RAW latency hidden.
#pragma unroll
            for (int mi = 0; mi < 4; mi++)
#pragma unroll
                for (int ni = 0; ni < 4; ni++)
                    MMA16816(acc[mi][ni], ah[mi], bh[ni * 2], bh[ni * 2 + 1]);
#pragma unroll
            for (int mi = 0; mi < 4; mi++)
#pragma unroll
                for (int ni = 0; ni < 4; ni++)
                    MMA16816(acc[mi][ni], ah[mi], bl[ni * 2], bl[ni * 2 + 1]);
#pragma unroll
            for (int mi = 0; mi < 4; mi++)
#pragma unroll
                for (int ni = 0; ni < 4; ni++)
                    MMA16816(acc[mi][ni], al[mi], bh[ni * 2], bh[ni * 2 + 1]);
        }
        __syncthreads();
    }

    const int g = lane >> 2, tg = lane & 3;
#pragma unroll
    for (int mi = 0; mi < 4; mi++) {
        const int row0 = bm + wy * 64 + mi * 16 + g;
#pragma unroll
        for (int ni = 0; ni < 4; ni++) {
            const int col = bn + wx * 32 + ni * 8 + tg * 2;
            float b0 = 0.f, b1 = 0.f;
            if (P.bias) { b0 = P.bias[col]; b1 = P.bias[col + 1]; }
            *(float2*)&P.C[(size_t)row0 * DIM + col] =
                make_float2(acc[mi][ni][0] + b0, acc[mi][ni][1] + b1);
            *(float2*)&P.C[(size_t)(row0 + 8) * DIM + col] =
                make_float2(acc[mi][ni][2] + b0, acc[mi][ni][3] + b1);
        }
    }
}

__global__ __launch_bounds__(256, 2) void gemm_mma(
    const __nv_bfloat16* __restrict__ Ah, const __nv_bfloat16* __restrict__ Al,
    const __nv_bfloat16* __restrict__ Wh, const __nv_bfloat16* __restrict__ Wl,
    const float* __restrict__ bias, float* __restrict__ C)
{
    extern __shared__ __nv_bfloat16 sm[];
    GemmPtrs P{Ah, Al, Wh, Wl, bias, C};
    gemm_body(P, blockIdx.y * 128, blockIdx.x * 128, sm);
}

__global__ __launch_bounds__(256, 2) void gemm_kv(
    const __nv_bfloat16* __restrict__ Ah, const __nv_bfloat16* __restrict__ Al,
    const __nv_bfloat16* __restrict__ Wkh, const __nv_bfloat16* __restrict__ Wkl,
    const __nv_bfloat16* __restrict__ Wvh, const __nv_bfloat16* __restrict__ Wvl,
    float* __restrict__ K, float* __restrict__ V)
{
    extern __shared__ __nv_bfloat16 sm[];
    const int bnv = blockIdx.x * 128;
    GemmPtrs P;
    P.Ah = Ah; P.Al = Al; P.bias = nullptr;
    int bn;
    if (bnv < 512) { P.Wh = Wkh; P.Wl = Wkl; P.C = K; bn = bnv; }
    else           { P.Wh = Wvh; P.Wl = Wvl; P.C = V; bn = bnv - 512; }
    gemm_body(P, blockIdx.y * 128, bn, sm);
}

// ---------------------------------------------------------------- attention
__global__ __launch_bounds__(128) void attn_kernel()
{
    const int b = blockIdx.x;
    const int h = blockIdx.y;
    const int t = threadIdx.x;
    const int m = b & 127;
    const int nj = m + 1;
    const size_t kvbase = (size_t)((b >> 7) * GRP_OFF + (m * (m + 1)) / 2);

    __shared__ float qs[NTOK][DH + 1];
    __shared__ float ps[NTOK][NLAT + 1];

#pragma unroll
    for (int u = 0; u < 8; u++) {
        int e = t + u * 128;
        qs[e >> 6][e & 63] = g_q[(size_t)(b * NTOK + (e >> 6)) * DIM + h * DH + (e & 63)];
    }
    __syncthreads();

    {
        const int i = t & 15;
        const int jg = t >> 4;
        for (int j = jg; j < nj; j += 8) {
            const float4* k4 = (const float4*)&g_k[(kvbase + j) * DIM + h * DH];
            float s = 0.f;
#pragma unroll
            for (int d4 = 0; d4 < 16; d4++) {
                float4 kk = k4[d4];
                s += qs[i][d4 * 4 + 0] * kk.x + qs[i][d4 * 4 + 1] * kk.y
                   + qs[i][d4 * 4 + 2] * kk.z + qs[i][d4 * 4 + 3] * kk.w;
            }
            ps[i][j] = s * 0.125f;
        }
    }
    __syncthreads();

    if (t < NTOK) {
        float mx = -1e30f;
        for (int j = 0; j < nj; j++) mx = fmaxf(mx, ps[t][j]);
        float s = 0.f;
        for (int j = 0; j < nj; j++) { float e = expf(ps[t][j] - mx); ps[t][j] = e; s += e; }
        float inv = 1.f / s;
        for (int j = 0; j < nj; j++) ps[t][j] *= inv;
    }
    __syncthreads();

    {
        const int d  = t & 63;
        const int i0 = t >> 6;
        float acc[8];
#pragma unroll
        for (int ii = 0; ii < 8; ii++) acc[ii] = 0.f;
        for (int j = 0; j < nj; j++) {
            float vv = g_v[(kvbase + j) * DIM + h * DH + d];
#pragma unroll
            for (int ii = 0; ii < 8; ii++)
                acc[ii] += ps[i0 + 2 * ii][j] * vv;
        }
#pragma unroll
        for (int ii = 0; ii < 8; ii++) {
            size_t idx = (size_t)(b * NTOK + i0 + 2 * ii) * DIM + h * DH + d;
            __nv_bfloat16 hv = __float2bfloat16(acc[ii]);
            g_ah[idx] = hv;
            g_al[idx] = __float2bfloat16(acc[ii] - __bfloat162float(hv));
        }
    }
}

// ---------------------------------------------------------------- launch
extern "C" void kernel_launch(void* const* d_in, const int* in_sizes, int n_in,
                              void* d_out, int out_size)
{
    const float* x  = (const float*)d_in[0];
    const float* l  = (const float*)d_in[1];
    const float* Wq = (const float*)d_in[2];
    const float* Wk = (const float*)d_in[3];
    const float* Wv = (const float*)d_in[4];
    const float* Wo = (const float*)d_in[5];
    const float* bo = (const float*)d_in[6];
    float* out = (float*)d_out;

    float *pq, *pk, *pv;
    __nv_bfloat16 *pxh, *pxl, *pah, *pal, *pwh, *pwl, *plh, *pll;
    cudaGetSymbolAddress((void**)&pq,  g_q);
    cudaGetSymbolAddress((void**)&pk,  g_k);
    cudaGetSymbolAddress((void**)&pv,  g_v);
    cudaGetSymbolAddress((void**)&pxh, g_xh);
    cudaGetSymbolAddress((void**)&pxl, g_xl);
    cudaGetSymbolAddress((void**)&pah, g_ah);
    cudaGetSymbolAddress((void**)&pal, g_al);
    cudaGetSymbolAddress((void**)&pwh, g_wh);
    cudaGetSymbolAddress((void**)&pwl, g_wl);
    cudaGetSymbolAddress((void**)&plh, g_lh);
    cudaGetSymbolAddress((void**)&pll, g_ll);

    cudaFuncSetAttribute(gemm_mma, cudaFuncAttributeMaxDynamicSharedMemorySize, SMEMSZ);
    cudaFuncSetAttribute(gemm_kv,  cudaFuncAttributeMaxDynamicSharedMemorySize, SMEMSZ);

    const int WSZ = DIM * DIM;

    conv_hilo<<<(MQ * DIM / 4 + 255) / 256, 256>>>(x, pxh, pxl, MQ * DIM / 4);
    conv_w<<<4 * WSZ / 4 / 256, 256>>>(Wq, Wk, Wv, Wo);
    gather_l<<<dim3(BATCH, NLAT), 128>>>(l);

    gemm_mma<<<dim3(4, MQ / 128), 256, SMEMSZ>>>(pxh, pxl, pwh + 0 * WSZ, pwl + 0 * WSZ, nullptr, pq);
    gemm_kv<<<dim3(8, MKV_C / 128), 256, SMEMSZ>>>(plh, pll,
                                                   pwh + 1 * WSZ, pwl + 1 * WSZ,
                                                   pwh + 2 * WSZ, pwl + 2 * WSZ, pk, pv);
    attn_kernel<<<dim3(BATCH, NH), 128>>>();
    gemm_mma<<<dim3(4, MQ / 128), 256, SMEMSZ>>>(pah, pal, pwh + 3 * WSZ, pwl + 3 * WSZ, bo, out);
}